// round 3
// baseline (speedup 1.0000x reference)
#include <cuda_runtime.h>
#include <cfloat>
#include <math.h>

// Shapes: z_e [32,64,32,32] f32, emb [1024,64] f32
// Outputs concatenated f32: z_st [32,64,32,32] | loss | perplexity | encodings [32768,1024]
#define NN 32768
#define KK 1024
#define LOSS_OFF 2097152
#define PPL_OFF  2097153
#define ENC_OFF  2097154

__device__ __align__(16) int   g_idx[NN];
__device__ float g_e2[KK];
__device__ float g_loss;
__device__ int   g_cnt[KK];

// ---------------- init: zero scratch, ||e_k||^2 with reference rounding ----------------
__global__ void k_init(const float* __restrict__ emb) {
    int t = threadIdx.x;            // 1024 threads
    g_cnt[t] = 0;
    if (t == 0) g_loss = 0.f;
    const float* row = emb + t * 64;
    float s = 0.f;
#pragma unroll
    for (int j = 0; j < 64; ++j)
        s = __fadd_rn(s, __fmul_rn(row[j], row[j]));   // mul-then-add, sequential (no FMA)
    g_e2[t] = s;
}

// ---------------- argmin emulating reference fp32 rounding chain ----------------
// reference: dist = fl( fl(xsum_n + e2_k) - fl(2 * dot_nk) ), argmin = first min.
// dot needs only fp32-faithful accuracy (bin analysis) -> fast packed f32x2 FMAs.
// xsum needs bit-exactness -> sequential fl(s + fl(x*x)), ascending j.
__device__ __forceinline__ unsigned long long ffma2(unsigned long long a,
                                                    unsigned long long b,
                                                    unsigned long long c) {
    unsigned long long r;
    asm("fma.rn.f32x2 %0, %1, %2, %3;" : "=l"(r) : "l"(a), "l"(b), "l"(c));
    return r;
}

__global__ void __launch_bounds__(128) k_argmin(const float* __restrict__ z_e,
                                                const float* __restrict__ emb) {
    __shared__ __align__(16) float se[128 * 64];   // 32 KB chunk of emb
    __shared__ float se2[128];
    const int t = threadIdx.x;
    const int n = blockIdx.x * 128 + t;            // vector id, 256 blocks
    const int b = n >> 10, hw = n & 1023;
    const float* xrow = z_e + (size_t)b * 65536 + hw;   // element d at xrow[d*1024]

    // load 64-dim vector into 32 f32x2 pairs; xsum sequentially (reference order)
    unsigned long long x2[32];
    float xsum = 0.f;
#pragma unroll
    for (int j = 0; j < 32; ++j) {
        float lo = xrow[(2 * j) * 1024];
        float hi = xrow[(2 * j + 1) * 1024];
        xsum = __fadd_rn(xsum, __fmul_rn(lo, lo));
        xsum = __fadd_rn(xsum, __fmul_rn(hi, hi));
        asm("mov.b64 %0, {%1, %2};" : "=l"(x2[j]) : "f"(lo), "f"(hi));
    }

    float best = FLT_MAX;
    int bidx = 0;

    for (int c = 0; c < 8; ++c) {                  // 8 chunks of 128 codes
        __syncthreads();
        const float4* src = ((const float4*)emb) + c * 2048;
        float4* dst = (float4*)se;
#pragma unroll
        for (int i = 0; i < 16; ++i) dst[t + i * 128] = src[t + i * 128];
        se2[t] = g_e2[c * 128 + t];
        __syncthreads();

#pragma unroll 2
        for (int k = 0; k < 128; ++k) {
            const ulonglong2* ep = (const ulonglong2*)(se + k * 64);
            unsigned long long a0 = 0, a1 = 0, a2 = 0, a3 = 0;
#pragma unroll
            for (int j = 0; j < 16; j += 2) {
                ulonglong2 e0 = ep[j];
                ulonglong2 e1 = ep[j + 1];
                a0 = ffma2(x2[2 * j + 0], e0.x, a0);
                a1 = ffma2(x2[2 * j + 1], e0.y, a1);
                a2 = ffma2(x2[2 * j + 2], e1.x, a2);
                a3 = ffma2(x2[2 * j + 3], e1.y, a3);
            }
            float l0, h0, l1, h1, l2, h2, l3, h3;
            asm("mov.b64 {%0,%1}, %2;" : "=f"(l0), "=f"(h0) : "l"(a0));
            asm("mov.b64 {%0,%1}, %2;" : "=f"(l1), "=f"(h1) : "l"(a1));
            asm("mov.b64 {%0,%1}, %2;" : "=f"(l2), "=f"(h2) : "l"(a2));
            asm("mov.b64 {%0,%1}, %2;" : "=f"(l3), "=f"(h3) : "l"(a3));
            float dot = ((l0 + h0) + (l1 + h1)) + ((l2 + h2) + (l3 + h3));
            // reference rounding chain: fl(fl(xsum + e2) - fl(2*dot))
            float T = __fadd_rn(xsum, se2[k]);
            float C = __fmul_rn(2.0f, dot);
            float dist = __fadd_rn(T, -C);
            if (dist < best) { best = dist; bidx = c * 128 + k; }  // strict < = first-min
        }
    }
    g_idx[n] = bidx;
    atomicAdd(&g_cnt[bidx], 1);
}

// ---------------- z_st output + loss partial sums ----------------
__global__ void __launch_bounds__(256) k_out(const float* __restrict__ z_e,
                                             const float* __restrict__ emb,
                                             float* __restrict__ out) {
    int i4 = blockIdx.x * 256 + threadIdx.x;       // float4 index, 524288 total
    int i = i4 << 2;
    int d = (i >> 10) & 63;
    int n = ((i >> 16) << 10) | (i & 1023);        // vector id for these 4 elems (w+0..3)
    float4 z = ((const float4*)z_e)[i4];
    int4 iv = *(const int4*)(g_idx + n);
    float q0 = emb[iv.x * 64 + d];
    float q1 = emb[iv.y * 64 + d];
    float q2 = emb[iv.z * 64 + d];
    float q3 = emb[iv.w * 64 + d];
    float t0 = __fadd_rn(q0, -z.x), t1 = __fadd_rn(q1, -z.y);
    float t2 = __fadd_rn(q2, -z.z), t3 = __fadd_rn(q3, -z.w);
    float4 o;
    o.x = __fadd_rn(z.x, t0); o.y = __fadd_rn(z.y, t1);   // z + (z_q - z), ref rounding
    o.z = __fadd_rn(z.z, t2); o.w = __fadd_rn(z.w, t3);
    ((float4*)out)[i4] = o;

    float s = t0 * t0 + t1 * t1 + t2 * t2 + t3 * t3;
#pragma unroll
    for (int off = 16; off; off >>= 1) s += __shfl_xor_sync(0xffffffffu, s, off);
    __shared__ float red[8];
    if ((threadIdx.x & 31) == 0) red[threadIdx.x >> 5] = s;
    __syncthreads();
    if (threadIdx.x == 0) {
        float bs = ((red[0] + red[1]) + (red[2] + red[3])) +
                   ((red[4] + red[5]) + (red[6] + red[7]));
        atomicAdd(&g_loss, bs);
    }
}

// ---------------- one-hot encodings (float2 stores: region only 8B-aligned) ----------------
__global__ void __launch_bounds__(256) k_enc(float* __restrict__ enc) {
    int j = blockIdx.x * 256 + threadIdx.x;        // float2 index, 16777216 total
    int row = j >> 9;                              // 512 float2 per row of K=1024
    int c = (j & 511) << 1;
    int idx = g_idx[row];
    float2 v;
    v.x = (idx == c)     ? 1.f : 0.f;
    v.y = (idx == c + 1) ? 1.f : 0.f;
    ((float2*)enc)[j] = v;
}

// ---------------- finalize loss + perplexity ----------------
__global__ void k_fin(float* __restrict__ out) {
    int t = threadIdx.x;                           // 1024 threads
    float p = (float)g_cnt[t] * (1.0f / 32768.0f);
    float s = p * logf(p + 1e-10f);
#pragma unroll
    for (int off = 16; off; off >>= 1) s += __shfl_xor_sync(0xffffffffu, s, off);
    __shared__ float red[32];
    if ((t & 31) == 0) red[t >> 5] = s;
    __syncthreads();
    if (t == 0) {
        float tot = 0.f;
        for (int i = 0; i < 32; ++i) tot += red[i];
        float m = g_loss * (1.0f / 2097152.0f);
        out[LOSS_OFF] = m + 0.25f * m;             // q_latent + 0.25*e_latent (equal values)
        out[PPL_OFF]  = expf(-tot);
    }
}

extern "C" void kernel_launch(void* const* d_in, const int* in_sizes, int n_in,
                              void* d_out, int out_size) {
    const float* z_e = (const float*)d_in[0];
    const float* emb = (const float*)d_in[1];
    float* out = (float*)d_out;

    k_init<<<1, 1024>>>(emb);
    k_argmin<<<256, 128>>>(z_e, emb);
    k_out<<<2048, 256>>>(z_e, emb, out);
    k_enc<<<65536, 256>>>(out + ENC_OFF);
    k_fin<<<1, 1024>>>(out);
}

// round 8
// speedup vs baseline: 1.5191x; 1.5191x over previous
#include <cuda_runtime.h>
#include <cfloat>
#include <math.h>

// Shapes: z_e [32,64,32,32] f32, emb [1024,64] f32
// Outputs f32: z_st [2097152] | loss | perplexity | encodings [32768*1024]
#define NN 32768
#define KK 1024
#define LOSS_OFF 2097152
#define PPL_OFF  2097153
#define ENC_OFF  2097154

__device__ __align__(16) int   g_idx[NN];
__device__ float g_e2[KK];
__device__ float g_loss;
__device__ int   g_cnt[KK];

// ---------------- init: zero scratch, ||e_k||^2 with reference rounding ----------------
__global__ void k_init(const float* __restrict__ emb) {
    int t = threadIdx.x;            // 1024 threads
    g_cnt[t] = 0;
    if (t == 0) g_loss = 0.f;
    const float* row = emb + t * 64;
    float s = 0.f;
#pragma unroll
    for (int j = 0; j < 64; ++j)
        s = __fadd_rn(s, __fmul_rn(row[j], row[j]));
    g_e2[t] = s;
}

__device__ __forceinline__ unsigned long long ffma2(unsigned long long a,
                                                    unsigned long long b,
                                                    unsigned long long c) {
    unsigned long long r;
    asm("fma.rn.f32x2 %0, %1, %2, %3;" : "=l"(r) : "l"(a), "l"(b), "l"(c));
    return r;
}

// ---------------- fused: register-tiled argmin + z_st + loss ----------------
// Block: 256 threads, 128 x-vectors, all 1024 codes in 8 chunks of 128.
// Thread tile: Mt=16 rows (ty=t>>5) x Nt=4 codes (code = chunk*128 + i*32 + tx).
// x-fragment LDS are warp-broadcast; e-tile padded to stride 68 -> conflict-free.
// Shared (dynamic, 102400 B):
//   sx   [128*64] f32   @0      (32768)
//   se   [128*68] f32   @32768  (34816)
//   sred [128*33] u64   @67584  (33792)   per-(row,tx) best key
//   sxs  [128]    f32   @101376 (512)
//   sidx [128]    i32   @101888 (512)
__global__ void __launch_bounds__(256, 1) k_main(const float* __restrict__ z_e,
                                                 const float* __restrict__ emb,
                                                 float* __restrict__ out) {
    extern __shared__ char smem_raw[];
    float* sx = (float*)smem_raw;
    float* se = (float*)(smem_raw + 32768);
    unsigned long long* sred = (unsigned long long*)(smem_raw + 67584);
    float* sxs = (float*)(smem_raw + 101376);
    int*   sidx = (int*)(smem_raw + 101888);

    const int t = threadIdx.x;
    const int nbase = blockIdx.x << 7;      // 256 blocks x 128 vectors
    const int b = nbase >> 10;              // block fully inside one batch image
    const int hw0 = nbase & 1023;
    const float* zb = z_e + ((size_t)b << 16) + hw0;

    // ---- load x tile [vec][d]; lanes span d -> conflict-free STS, L1-reused LDG ----
    {
        int d0 = t & 31, g = t >> 5;
#pragma unroll
        for (int half = 0; half < 2; ++half) {
            int d = d0 + (half << 5);
            const float* src = zb + ((size_t)d << 10);
#pragma unroll
            for (int v = 0; v < 16; ++v) {
                int vec = (g << 4) + v;
                sx[(vec << 6) + d] = src[vec];
            }
        }
    }
    const int tx = t & 31, ty = t >> 5;
    // init per-(row,tx) reduction slots
#pragma unroll
    for (int r = 0; r < 16; ++r)
        sred[((ty << 4) + r) * 33 + tx] = ~0ull;
    __syncthreads();

    // xsum: strict sequential reference order fl(s + fl(x*x))
    if (t < 128) {
        const float* xr = sx + (t << 6);
        float s = 0.f;
#pragma unroll
        for (int j = 0; j < 64; ++j)
            s = __fadd_rn(s, __fmul_rn(xr[j], xr[j]));
        sxs[t] = s;
    }

    for (int c = 0; c < 8; ++c) {
        __syncthreads();                    // protect se reuse; c=0: orders sxs
        // load e chunk [128 codes][64] -> stride-68 padded smem
        {
            const float* ec = emb + (c << 13);
#pragma unroll
            for (int q = 0; q < 32; ++q) {
                int idx = t + (q << 8);
                int code = idx >> 6, d = idx & 63;
                se[code * 68 + d] = ec[idx];
            }
        }
        __syncthreads();

        unsigned long long acc[64];
#pragma unroll
        for (int i = 0; i < 64; ++i) acc[i] = 0ull;

#pragma unroll
        for (int ds = 0; ds < 16; ++ds) {   // 4 floats (2 f32x2) per step
            ulonglong2 ef[4];
#pragma unroll
            for (int i = 0; i < 4; ++i)     // code = i*32+tx: bank step 4 -> conflict-free
                ef[i] = *(const ulonglong2*)(se + ((i << 5) + tx) * 68 + (ds << 2));
#pragma unroll
            for (int sub = 0; sub < 4; ++sub) {
                ulonglong2 xf[4];
#pragma unroll
                for (int r = 0; r < 4; ++r) // warp-uniform address -> broadcast
                    xf[r] = *(const ulonglong2*)(sx + (((ty << 4) + (sub << 2) + r) << 6) + (ds << 2));
#pragma unroll
                for (int r = 0; r < 4; ++r)
#pragma unroll
                    for (int i = 0; i < 4; ++i) {
                        int a = (((sub << 2) + r) << 2) + i;
                        acc[a] = ffma2(xf[r].x, ef[i].x, acc[a]);
                        acc[a] = ffma2(xf[r].y, ef[i].y, acc[a]);
                    }
            }
        }

        // epilogue: reference rounding chain, strict-< (k ascending within thread)
#pragma unroll
        for (int r = 0; r < 16; ++r) {
            float xs = sxs[(ty << 4) + r];
            float bd = 0.f; int bk = 0;
#pragma unroll
            for (int i = 0; i < 4; ++i) {
                float lo, hi;
                asm("mov.b64 {%0,%1}, %2;" : "=f"(lo), "=f"(hi) : "l"(acc[(r << 2) + i]));
                float dot = __fadd_rn(lo, hi);
                float e2v = g_e2[(c << 7) + (i << 5) + tx];
                float T = __fadd_rn(xs, e2v);
                float dist = __fmaf_rn(dot, -2.0f, T);   // == fl(T - fl(2*dot)), 2*dot exact
                int k = (c << 7) + (i << 5) + tx;
                if (i == 0 || dist < bd) { bd = dist; bk = k; }
            }
            // dist >= 0 always -> float bits monotonic as uint; key min == (dist, k) lexicographic
            unsigned long long key = ((unsigned long long)__float_as_uint(bd) << 32) | (unsigned)bk;
            unsigned long long* slot = &sred[((ty << 4) + r) * 33 + tx];
            if (key < *slot) *slot = key;
        }
    }
    __syncthreads();

    // final per-row reduce over 32 tx slots
    if (t < 128) {
        const unsigned long long* rowp = sred + t * 33;
        unsigned long long best = rowp[0];
#pragma unroll
        for (int j = 1; j < 32; ++j) {
            unsigned long long v = rowp[j];
            if (v < best) best = v;
        }
        int k = (int)(best & 0xffffffffu);
        sidx[t] = k;
        g_idx[nbase + t] = k;
        atomicAdd(&g_cnt[k], 1);
    }
    __syncthreads();

    // fused z_st + loss: lanes span vec -> coalesced 128B stores
    {
        float s = 0.f;
        int lane = t & 31, wg = t >> 5;
        float* ob = out + ((size_t)b << 16) + hw0;
#pragma unroll
        for (int dd = 0; dd < 8; ++dd) {
            int d = wg + (dd << 3);
#pragma unroll
            for (int vc = 0; vc < 4; ++vc) {
                int vec = lane + (vc << 5);
                float z = sx[(vec << 6) + d];
                int idx = sidx[vec];
                float qv = emb[(idx << 6) + d];
                float tt = __fadd_rn(qv, -z);
                ob[((size_t)d << 10) + vec] = __fadd_rn(z, tt);  // z + (z_q - z), ref rounding
                s = __fmaf_rn(tt, tt, s);
            }
        }
#pragma unroll
        for (int off = 16; off; off >>= 1) s += __shfl_xor_sync(0xffffffffu, s, off);
        if (lane == 0) atomicAdd(&g_loss, s);
    }
}

// ---------------- scatter ones into zeroed encodings ----------------
__global__ void __launch_bounds__(256) k_enc1(float* __restrict__ out) {
    int n = blockIdx.x * 256 + threadIdx.x;        // 32768 threads
    out[(size_t)ENC_OFF + ((size_t)n << 10) + g_idx[n]] = 1.0f;
}

// ---------------- finalize loss + perplexity ----------------
__global__ void k_fin(float* __restrict__ out) {
    int t = threadIdx.x;                           // 1024 threads
    float p = (float)g_cnt[t] * (1.0f / 32768.0f);
    float s = p * logf(p + 1e-10f);
#pragma unroll
    for (int off = 16; off; off >>= 1) s += __shfl_xor_sync(0xffffffffu, s, off);
    __shared__ float red[32];
    if ((t & 31) == 0) red[t >> 5] = s;
    __syncthreads();
    if (t == 0) {
        float tot = 0.f;
        for (int i = 0; i < 32; ++i) tot += red[i];
        float m = g_loss * (1.0f / 2097152.0f);
        out[LOSS_OFF] = m + 0.25f * m;
        out[PPL_OFF]  = expf(-tot);
    }
}

extern "C" void kernel_launch(void* const* d_in, const int* in_sizes, int n_in,
                              void* d_out, int out_size) {
    const float* z_e = (const float*)d_in[0];
    const float* emb = (const float*)d_in[1];
    float* out = (float*)d_out;

    cudaFuncSetAttribute(k_main, cudaFuncAttributeMaxDynamicSharedMemorySize, 102400);

    k_init<<<1, 1024>>>(emb);
    cudaMemsetAsync(out + ENC_OFF, 0, (size_t)33554432 * 4);
    k_main<<<256, 256, 102400>>>(z_e, emb, out);
    k_enc1<<<128, 256>>>(out);
    k_fin<<<1, 1024>>>(out);
}

// round 11
// speedup vs baseline: 1.6037x; 1.0557x over previous
#include <cuda_runtime.h>
#include <cfloat>
#include <math.h>

// Shapes: z_e [32,64,32,32] f32, emb [1024,64] f32
// Outputs f32: z_st [2097152] | loss | perplexity | encodings [32768*1024]
#define NN 32768
#define KK 1024
#define LOSS_OFF 2097152
#define PPL_OFF  2097153
#define ENC_OFF  2097154

__device__ float g_e2[KK];
__device__ float g_loss;
__device__ int   g_cnt[KK];

// ---------------- init: zero scratch, ||e_k||^2 with reference rounding ----------------
__global__ void k_init(const float* __restrict__ emb) {
    int t = threadIdx.x;            // 1024 threads
    g_cnt[t] = 0;
    if (t == 0) g_loss = 0.f;
    const float* row = emb + t * 64;
    float s = 0.f;
#pragma unroll
    for (int j = 0; j < 64; ++j)
        s = __fadd_rn(s, __fmul_rn(row[j], row[j]));
    g_e2[t] = s;
}

__device__ __forceinline__ unsigned long long ffma2(unsigned long long a,
                                                    unsigned long long b,
                                                    unsigned long long c) {
    unsigned long long r;
    asm("fma.rn.f32x2 %0, %1, %2, %3;" : "=l"(r) : "l"(a), "l"(b), "l"(c));
    return r;
}

// ---------------- fused: argmin + z_st + loss + encodings (zeros AND ones) ----------------
// Block: 256 threads, 128 x-vectors, all 1024 codes in 8 chunks of 128.
// Thread tile: Mt=16 rows (ty=t>>5) x Nt=4 codes (code = chunk*128 + i*32 + tx).
// Encodings: each block owns rows [nbase, nbase+128) = 512KB slab; zeros are
// streamed out during the chunk loop (overlaps FFMA-bound compute), the single
// '1' per row is written after the final reduce (ordered by __syncthreads).
// Shared (dynamic, 102400 B): sx[128*64] | se[128*68] | sred[128*33]u64 | sxs[128] | sidx[128]
__global__ void __launch_bounds__(256, 1) k_main(const float* __restrict__ z_e,
                                                 const float* __restrict__ emb,
                                                 float* __restrict__ out) {
    extern __shared__ char smem_raw[];
    float* sx = (float*)smem_raw;
    float* se = (float*)(smem_raw + 32768);
    unsigned long long* sred = (unsigned long long*)(smem_raw + 67584);
    float* sxs = (float*)(smem_raw + 101376);
    int*   sidx = (int*)(smem_raw + 101888);

    const int t = threadIdx.x;
    const int nbase = blockIdx.x << 7;      // 256 blocks x 128 vectors
    const int b = nbase >> 10;              // block fully inside one batch image
    const int hw0 = nbase & 1023;
    const float* zb = z_e + ((size_t)b << 16) + hw0;
    float* encf = out + (size_t)ENC_OFF + ((size_t)nbase << 10);   // 8B-aligned slab
    float2* enc2 = (float2*)encf;                                  // 65536 float2

    // ---- load x tile [vec][d]; lanes span d -> conflict-free STS, L1-reused LDG ----
    {
        int d0 = t & 31, g = t >> 5;
#pragma unroll
        for (int half = 0; half < 2; ++half) {
            int d = d0 + (half << 5);
            const float* src = zb + ((size_t)d << 10);
#pragma unroll
            for (int v = 0; v < 16; ++v) {
                int vec = (g << 4) + v;
                sx[(vec << 6) + d] = src[vec];
            }
        }
    }
    const int tx = t & 31, ty = t >> 5;
#pragma unroll
    for (int r = 0; r < 16; ++r)
        sred[((ty << 4) + r) * 33 + tx] = ~0ull;
    __syncthreads();

    // xsum: strict sequential reference order fl(s + fl(x*x))
    if (t < 128) {
        const float* xr = sx + (t << 6);
        float s = 0.f;
#pragma unroll
        for (int j = 0; j < 64; ++j)
            s = __fadd_rn(s, __fmul_rn(xr[j], xr[j]));
        sxs[t] = s;
    }

    for (int c = 0; c < 8; ++c) {
        __syncthreads();                    // protect se reuse; c=0: orders sxs
        // load e chunk [128 codes][64] -> stride-68 padded smem; hoist e2 loads
        float e2r[4];
        {
            const float* ec = emb + (c << 13);
#pragma unroll
            for (int q = 0; q < 32; ++q) {
                int idx = t + (q << 8);
                int code = idx >> 6, d = idx & 63;
                se[code * 68 + d] = ec[idx];
            }
#pragma unroll
            for (int i = 0; i < 4; ++i)
                e2r[i] = g_e2[(c << 7) + (i << 5) + tx];
        }
        __syncthreads();

        // stream 1/8 of this block's encodings-zero slab (overlaps with FFMA)
        {
            float2 z2; z2.x = 0.f; z2.y = 0.f;
            float2* dst = enc2 + (c << 13);
#pragma unroll
            for (int q = 0; q < 32; ++q)
                dst[(q << 8) + t] = z2;
        }

        unsigned long long acc[64];
#pragma unroll
        for (int i = 0; i < 64; ++i) acc[i] = 0ull;

#pragma unroll
        for (int ds = 0; ds < 16; ++ds) {   // 4 floats (2 f32x2) per step
            ulonglong2 ef[4];
#pragma unroll
            for (int i = 0; i < 4; ++i)     // code = i*32+tx: bank step 4 -> conflict-free
                ef[i] = *(const ulonglong2*)(se + ((i << 5) + tx) * 68 + (ds << 2));
#pragma unroll
            for (int sub = 0; sub < 4; ++sub) {
                ulonglong2 xf[4];
#pragma unroll
                for (int r = 0; r < 4; ++r) // warp-uniform address -> broadcast
                    xf[r] = *(const ulonglong2*)(sx + (((ty << 4) + (sub << 2) + r) << 6) + (ds << 2));
#pragma unroll
                for (int r = 0; r < 4; ++r)
#pragma unroll
                    for (int i = 0; i < 4; ++i) {
                        int a = (((sub << 2) + r) << 2) + i;
                        acc[a] = ffma2(xf[r].x, ef[i].x, acc[a]);
                        acc[a] = ffma2(xf[r].y, ef[i].y, acc[a]);
                    }
            }
        }

        // epilogue: reference rounding chain, strict-< (k ascending within thread)
#pragma unroll
        for (int r = 0; r < 16; ++r) {
            float xs = sxs[(ty << 4) + r];
            float bd = 0.f; int bk = 0;
#pragma unroll
            for (int i = 0; i < 4; ++i) {
                float lo, hi;
                asm("mov.b64 {%0,%1}, %2;" : "=f"(lo), "=f"(hi) : "l"(acc[(r << 2) + i]));
                float dot = __fadd_rn(lo, hi);
                float T = __fadd_rn(xs, e2r[i]);
                float dist = __fmaf_rn(dot, -2.0f, T);   // == fl(T - fl(2*dot)), 2*dot exact
                int k = (c << 7) + (i << 5) + tx;
                if (i == 0 || dist < bd) { bd = dist; bk = k; }
            }
            // dist >= 0 -> float bits monotonic as uint; u64 min == (dist, k) lexicographic
            unsigned long long key = ((unsigned long long)__float_as_uint(bd) << 32) | (unsigned)bk;
            unsigned long long* slot = &sred[((ty << 4) + r) * 33 + tx];
            if (key < *slot) *slot = key;
        }
    }
    __syncthreads();                        // also orders all zero-stores before the '1's

    // final per-row reduce over 32 tx slots; write the one-hot '1'
    if (t < 128) {
        const unsigned long long* rowp = sred + t * 33;
        unsigned long long best = rowp[0];
#pragma unroll
        for (int j = 1; j < 32; ++j) {
            unsigned long long v = rowp[j];
            if (v < best) best = v;
        }
        int k = (int)(best & 0xffffffffu);
        sidx[t] = k;
        encf[((size_t)t << 10) + k] = 1.0f;
        atomicAdd(&g_cnt[k], 1);
    }
    __syncthreads();

    // fused z_st + loss: lanes span vec -> coalesced 128B stores
    {
        float s = 0.f;
        int lane = t & 31, wg = t >> 5;
        float* ob = out + ((size_t)b << 16) + hw0;
#pragma unroll
        for (int dd = 0; dd < 8; ++dd) {
            int d = wg + (dd << 3);
#pragma unroll
            for (int vc = 0; vc < 4; ++vc) {
                int vec = lane + (vc << 5);
                float z = sx[(vec << 6) + d];
                int idx = sidx[vec];
                float qv = emb[(idx << 6) + d];
                float tt = __fadd_rn(qv, -z);
                ob[((size_t)d << 10) + vec] = __fadd_rn(z, tt);  // z + (z_q - z), ref rounding
                s = __fmaf_rn(tt, tt, s);
            }
        }
#pragma unroll
        for (int off = 16; off; off >>= 1) s += __shfl_xor_sync(0xffffffffu, s, off);
        if (lane == 0) atomicAdd(&g_loss, s);
    }
}

// ---------------- finalize loss + perplexity ----------------
__global__ void k_fin(float* __restrict__ out) {
    int t = threadIdx.x;                           // 1024 threads
    float p = (float)g_cnt[t] * (1.0f / 32768.0f);
    float s = p * logf(p + 1e-10f);
#pragma unroll
    for (int off = 16; off; off >>= 1) s += __shfl_xor_sync(0xffffffffu, s, off);
    __shared__ float red[32];
    if ((t & 31) == 0) red[t >> 5] = s;
    __syncthreads();
    if (t == 0) {
        float tot = 0.f;
        for (int i = 0; i < 32; ++i) tot += red[i];
        float m = g_loss * (1.0f / 2097152.0f);
        out[LOSS_OFF] = m + 0.25f * m;
        out[PPL_OFF]  = expf(-tot);
    }
}

extern "C" void kernel_launch(void* const* d_in, const int* in_sizes, int n_in,
                              void* d_out, int out_size) {
    const float* z_e = (const float*)d_in[0];
    const float* emb = (const float*)d_in[1];
    float* out = (float*)d_out;

    cudaFuncSetAttribute(k_main, cudaFuncAttributeMaxDynamicSharedMemorySize, 102400);

    k_init<<<1, 1024>>>(emb);
    k_main<<<256, 256, 102400>>>(z_e, emb, out);
    k_fin<<<1, 1024>>>(out);
}